// round 14
// baseline (speedup 1.0000x reference)
#include <cuda_runtime.h>
#include <cuda_fp16.h>

#define NMAX 200000
#define SLACK 96                       // max supported degree per node (Poisson(32) tail ~4e-20)

// ---------------- static device scratch ----------------
static __device__ __align__(16) int g_csr[NMAX * SLACK];  // slack CSR: row i at [96*i, cursor[i])
static __device__ int   g_cursor[NMAX];
static __device__ float g_dinv[NMAX];
static __device__ float g_xw[NMAX * 16];       // fp32 x@W_in (pre-dinv)
static __device__ uint2 g_hA[NMAX * 4];        // layer-0 scaled input; then per-layer fp16 y
static __device__ uint2 g_hB[NMAX * 4];        // pre-scaled fp16x4 quarter-rows (agg input)
static __device__ float g_stats[4 * 32];       // per mid-layer [sum16, sumsq16] of y

// ---------------- helpers ----------------

// int64 entries (node ids < 2^31) have zero high words; int32 layout puts
// node ids there instead.
__device__ __forceinline__ bool is64_layout(const int* __restrict__ ei, int E) {
    int m = (E < 1024) ? E : 1024;
    int any = 0;
    for (int k = threadIdx.x; k < m; k += blockDim.x) any |= ei[2 * k + 1];
    return __syncthreads_or(any) == 0;
}

// ---------------- prep ----------------

// cursor[i] = SLACK*i; block 0 zeroes the BN stats.
__global__ void k_init(int n) {
    int i = blockIdx.x * blockDim.x + threadIdx.x;
    if (i < n) g_cursor[i] = i * SLACK;
    if (blockIdx.x == 0 && threadIdx.x < 128) g_stats[threadIdx.x] = 0.0f;
}

// Fused kernel: blocks [0, nbn) compute g_xw = x@W_in (fp32, DRAM+FMA bound,
// scheduled first so DRAM reads start in wave 1); blocks [nbn, nbn+nbe4) fill
// the slack CSR in a single atomic pass (LTS-atomic bound).
// __launch_bounds__(256, 8) caps regs at 32 so the fill half keeps occupancy.
__global__ void __launch_bounds__(256, 8)
k_fill_xw(const int* __restrict__ ei, int E,
          const float* __restrict__ x, const float* __restrict__ W,
          int n, int nbn) {
    int tid = threadIdx.x;
    if ((int)blockIdx.x >= nbn) {
        // ---- CSR fill: 4 edges per thread ----
        bool is64 = is64_layout(ei, E);
        int t = ((int)blockIdx.x - nbn) * blockDim.x + tid;
        int e0 = t * 4;
        bool vec = is64 ? ((E & 1) == 0) : ((E & 3) == 0);
        if (vec && e0 + 4 <= E) {
            int s0, s1, s2, s3, d0, d1, d2, d3;
            if (is64) {
                const int4* ps = (const int4*)ei;
                const int4* pd = (const int4*)(ei + 2 * E);
                int4 sa = ps[2 * t], sb = ps[2 * t + 1];
                int4 da = pd[2 * t], db = pd[2 * t + 1];
                s0 = sa.x; s1 = sa.z; s2 = sb.x; s3 = sb.z;
                d0 = da.x; d1 = da.z; d2 = db.x; d3 = db.z;
            } else {
                int4 s = ((const int4*)ei)[t];
                int4 d = ((const int4*)(ei + E))[t];
                s0 = s.x; s1 = s.y; s2 = s.z; s3 = s.w;
                d0 = d.x; d1 = d.y; d2 = d.z; d3 = d.w;
            }
            int p0 = atomicAdd(&g_cursor[d0], 1);
            int p1 = atomicAdd(&g_cursor[d1], 1);
            int p2 = atomicAdd(&g_cursor[d2], 1);
            int p3 = atomicAdd(&g_cursor[d3], 1);
            g_csr[p0] = s0;
            g_csr[p1] = s1;
            g_csr[p2] = s2;
            g_csr[p3] = s3;
        } else {
            for (int e = e0; e < E && e < e0 + 4; e++) {
                int s, d;
                if (is64) { s = ei[2 * e]; d = ei[2 * E + 2 * e]; }
                else      { s = ei[e];     d = ei[E + e]; }
                g_csr[atomicAdd(&g_cursor[d], 1)] = s;
            }
        }
    } else {
        // ---- input projection: g_xw = x @ W_in (fp32, no dinv yet) ----
        __shared__ float sW[64 * 16];
        ((float4*)sW)[tid] = ((const float4*)W)[tid];
        __syncthreads();
        int row = (int)blockIdx.x * 256 + tid;
        if (row >= n) return;
        const float4* xr = (const float4*)(x + (size_t)row * 64);
        float y[16];
#pragma unroll
        for (int j = 0; j < 16; j++) y[j] = 0.0f;
#pragma unroll
        for (int k4 = 0; k4 < 16; k4++) {
            float4 xv = xr[k4];
            int kb = k4 * 4;
#pragma unroll
            for (int j = 0; j < 16; j++) y[j] += xv.x * sW[(kb + 0) * 16 + j];
#pragma unroll
            for (int j = 0; j < 16; j++) y[j] += xv.y * sW[(kb + 1) * 16 + j];
#pragma unroll
            for (int j = 0; j < 16; j++) y[j] += xv.z * sW[(kb + 2) * 16 + j];
#pragma unroll
            for (int j = 0; j < 16; j++) y[j] += xv.w * sW[(kb + 3) * 16 + j];
        }
        float4* o = (float4*)(g_xw + (size_t)row * 16);
        o[0] = make_float4(y[0], y[1], y[2], y[3]);
        o[1] = make_float4(y[4], y[5], y[6], y[7]);
        o[2] = make_float4(y[8], y[9], y[10], y[11]);
        o[3] = make_float4(y[12], y[13], y[14], y[15]);
    }
}

// post-fill: dinv from cursor-derived degree; g_hA = fp16(dinv * g_xw)
__global__ void k_post(int n) {
    int i = blockIdx.x * blockDim.x + threadIdx.x;
    if (i >= n) return;
    int deg = g_cursor[i] - i * SLACK;
    float di = rsqrtf((float)deg + 1.0f);  // +1 self loop
    g_dinv[i] = di;
    const float4* X = (const float4*)(g_xw + (size_t)i * 16);
    uint2* o = g_hA + (size_t)i * 4;
#pragma unroll
    for (int q = 0; q < 4; q++) {
        float4 v = X[q];
        __half2 lo = __float22half2_rn(make_float2(v.x * di, v.y * di));
        __half2 hi = __float22half2_rn(make_float2(v.z * di, v.w * di));
        o[q] = make_uint2(*(unsigned*)&lo, *(unsigned*)&hi);
    }
}

// ---------------- aggregation core ----------------
// 4 lanes per node; lane q owns channels [4q,4q+4). Features pre-scaled (hs=dinv*h):
// sum_raw = sum_{s in N(d)} hs[s] + hs[d]; caller scales by dinv[d].
// Row extent: [SLACK*i, cursor[i]). CSR entries shared via width-4 shuffles.
// Edge PAIRS are pre-reduced in fp16 (2 HADD2) before conversion, cutting the
// convert+add instruction stream ~30% (issue-bound per ncu R13).
__device__ __forceinline__ float4 agg_core(const uint2* __restrict__ H, int i, int q,
                                           unsigned gmask) {
    uint2 self = H[(size_t)i * 4 + q];
    float2 slo = __half22float2(*(const __half2*)&self.x);
    float2 shi = __half22float2(*(const __half2*)&self.y);
    float4 acc = make_float4(slo.x, slo.y, shi.x, shi.y);
    int e = i * SLACK;
    int e1 = g_cursor[i];
    for (; e + 8 <= e1; e += 8) {
        int sA = g_csr[e + q];
        int sB = g_csr[e + 4 + q];
#pragma unroll
        for (int r = 0; r < 4; r++) {
            int s0 = __shfl_sync(gmask, sA, r, 4);
            int s1 = __shfl_sync(gmask, sB, r, 4);
            uint2 v0 = H[(size_t)s0 * 4 + q];
            uint2 v1 = H[(size_t)s1 * 4 + q];
            __half2 plo = __hadd2(*(const __half2*)&v0.x, *(const __half2*)&v1.x);
            __half2 phi = __hadd2(*(const __half2*)&v0.y, *(const __half2*)&v1.y);
            float2 l = __half22float2(plo);
            float2 h = __half22float2(phi);
            acc.x += l.x; acc.y += l.y; acc.z += h.x; acc.w += h.y;
        }
    }
    if (e + 4 <= e1) {
        int sA = g_csr[e + q];
#pragma unroll
        for (int r = 0; r < 2; r++) {
            int s0 = __shfl_sync(gmask, sA, 2 * r + 0, 4);
            int s1 = __shfl_sync(gmask, sA, 2 * r + 1, 4);
            uint2 v0 = H[(size_t)s0 * 4 + q];
            uint2 v1 = H[(size_t)s1 * 4 + q];
            __half2 plo = __hadd2(*(const __half2*)&v0.x, *(const __half2*)&v1.x);
            __half2 phi = __hadd2(*(const __half2*)&v0.y, *(const __half2*)&v1.y);
            float2 l = __half22float2(plo);
            float2 h = __half22float2(phi);
            acc.x += l.x; acc.y += l.y; acc.z += h.x; acc.w += h.y;
        }
        e += 4;
    }
    for (; e < e1; e++) {
        int s = g_csr[e];
        uint2 v = H[(size_t)s * 4 + q];
        float2 lo = __half22float2(*(const __half2*)&v.x);
        float2 hi = __half22float2(*(const __half2*)&v.y);
        acc.x += lo.x; acc.y += lo.y; acc.z += hi.x; acc.w += hi.y;
    }
    return acc;
}

// input layer: h1 = dinv[d]*sum + b_in; store hB = fp16(dinv[d] * h1)
__global__ void k_agg_in(const float* __restrict__ b, int n) {
    int idx = blockIdx.x * blockDim.x + threadIdx.x;
    if (idx >= n * 4) return;
    int i = idx >> 2, q = idx & 3;
    unsigned gmask = 0xFu << ((threadIdx.x & 31) & ~3);
    float4 acc = agg_core(g_hA, i, q, gmask);
    float di = g_dinv[i];
    float4 bb = ((const float4*)b)[q];
    acc.x = (acc.x * di + bb.x) * di;
    acc.y = (acc.y * di + bb.y) * di;
    acc.z = (acc.z * di + bb.z) * di;
    acc.w = (acc.w * di + bb.w) * di;
    __half2 lo = __float22half2_rn(make_float2(acc.x, acc.y));
    __half2 hi = __float22half2_rn(make_float2(acc.z, acc.w));
    g_hB[(size_t)i * 4 + q] = make_uint2(*(unsigned*)&lo, *(unsigned*)&hi);
}

// mid agg: compute a = dinv[d]*sum, y = a@W + b; store y as fp16 into g_hA,
// and accumulate per-channel sum/sumsq of y into stats.
__global__ void k_agg_mid(const float* __restrict__ W, const float* __restrict__ b,
                          float* __restrict__ stats, int n) {
    __shared__ float sW[256];
    __shared__ float sB[16];
    __shared__ float sSum[16], sSq[16];
    int tid = threadIdx.x;
    sW[tid] = W[tid];
    if (tid < 16) { sB[tid] = b[tid]; sSum[tid] = 0.0f; sSq[tid] = 0.0f; }
    __syncthreads();
    int idx = blockIdx.x * blockDim.x + tid;
    bool valid = idx < n * 4;
    int i = valid ? (idx >> 2) : 0;
    int q = idx & 3;
    int lane = tid & 31;
    unsigned gmask = 0xFu << (lane & ~3);
    float4 acc = agg_core(g_hB, i, q, gmask);
    float di = g_dinv[i];
    acc.x *= di; acc.y *= di; acc.z *= di; acc.w *= di;
    // assemble full 16-vector of node i across the 4-lane group
    float af[16];
    int base = lane & ~3;
#pragma unroll
    for (int r = 0; r < 4; r++) {
        af[r * 4 + 0] = __shfl_sync(0xFFFFFFFFu, acc.x, base + r);
        af[r * 4 + 1] = __shfl_sync(0xFFFFFFFFu, acc.y, base + r);
        af[r * 4 + 2] = __shfl_sync(0xFFFFFFFFu, acc.z, base + r);
        af[r * 4 + 3] = __shfl_sync(0xFFFFFFFFu, acc.w, base + r);
    }
    // this lane computes y for its 4 channels
    float s4[4], q4[4];
#pragma unroll
    for (int m = 0; m < 4; m++) {
        float y = sB[q * 4 + m];
#pragma unroll
        for (int k = 0; k < 16; k++) y += af[k] * sW[k * 16 + q * 4 + m];
        if (!valid) y = 0.0f;
        s4[m] = y;
        q4[m] = y * y;
    }
    // store y as fp16 (before the stats reduction clobbers s4)
    if (valid) {
        __half2 lo = __float22half2_rn(make_float2(s4[0], s4[1]));
        __half2 hi = __float22half2_rn(make_float2(s4[2], s4[3]));
        g_hA[(size_t)i * 4 + q] = make_uint2(*(unsigned*)&lo, *(unsigned*)&hi);
    }
    // reduce across the 8 groups in the warp
#pragma unroll
    for (int off = 4; off < 32; off <<= 1) {
#pragma unroll
        for (int m = 0; m < 4; m++) {
            s4[m] += __shfl_xor_sync(0xFFFFFFFFu, s4[m], off);
            q4[m] += __shfl_xor_sync(0xFFFFFFFFu, q4[m], off);
        }
    }
    if (lane < 4) {
#pragma unroll
        for (int m = 0; m < 4; m++) {
            atomicAdd(&sSum[lane * 4 + m], s4[m]);
            atomicAdd(&sSq[lane * 4 + m], q4[m]);
        }
    }
    __syncthreads();
    if (tid < 16) {
        atomicAdd(&stats[tid], sSum[tid]);
        atomicAdd(&stats[16 + tid], sSq[tid]);
    }
}

// head agg + dual matmul + relu fused: out = [relu(a@Wsin+bsin); relu(a@Wcos+bcos)]
__global__ void k_agg_head(const float* __restrict__ Wsin, const float* __restrict__ bsin,
                           const float* __restrict__ Wcos, const float* __restrict__ bcos,
                           float* __restrict__ out, int n) {
    __shared__ float sWs[256], sWc[256];
    __shared__ float sBs[16], sBc[16];
    int tid = threadIdx.x;
    sWs[tid] = Wsin[tid];
    sWc[tid] = Wcos[tid];
    if (tid < 16) { sBs[tid] = bsin[tid]; sBc[tid] = bcos[tid]; }
    __syncthreads();
    int idx = blockIdx.x * blockDim.x + tid;
    bool valid = idx < n * 4;
    int i = valid ? (idx >> 2) : 0;
    int q = idx & 3;
    int lane = tid & 31;
    unsigned gmask = 0xFu << (lane & ~3);
    float4 acc = agg_core(g_hB, i, q, gmask);
    float di = g_dinv[i];
    acc.x *= di; acc.y *= di; acc.z *= di; acc.w *= di;
    float af[16];
    int base = lane & ~3;
#pragma unroll
    for (int r = 0; r < 4; r++) {
        af[r * 4 + 0] = __shfl_sync(0xFFFFFFFFu, acc.x, base + r);
        af[r * 4 + 1] = __shfl_sync(0xFFFFFFFFu, acc.y, base + r);
        af[r * 4 + 2] = __shfl_sync(0xFFFFFFFFu, acc.z, base + r);
        af[r * 4 + 3] = __shfl_sync(0xFFFFFFFFu, acc.w, base + r);
    }
    if (!valid) return;
    float ys[4], yc[4];
#pragma unroll
    for (int m = 0; m < 4; m++) { ys[m] = sBs[q * 4 + m]; yc[m] = sBc[q * 4 + m]; }
#pragma unroll
    for (int k = 0; k < 16; k++) {
        float av = af[k];
#pragma unroll
        for (int m = 0; m < 4; m++) {
            ys[m] += av * sWs[k * 16 + q * 4 + m];
            yc[m] += av * sWc[k * 16 + q * 4 + m];
        }
    }
    float4 os = make_float4(fmaxf(ys[0], 0.0f), fmaxf(ys[1], 0.0f),
                            fmaxf(ys[2], 0.0f), fmaxf(ys[3], 0.0f));
    float4 oc = make_float4(fmaxf(yc[0], 0.0f), fmaxf(yc[1], 0.0f),
                            fmaxf(yc[2], 0.0f), fmaxf(yc[3], 0.0f));
    ((float4*)(out))[(size_t)i * 4 + q] = os;
    ((float4*)(out + (size_t)n * 16))[(size_t)i * 4 + q] = oc;
}

// hB = fp16(dinv * relu(y*sc + shift))  — streams fp16 y from g_hA.
// Bias is already inside y, so shift = beta - mean*sc.
__global__ void k_bn_relu(const float* __restrict__ stats,
                          const float* __restrict__ gamma, const float* __restrict__ beta,
                          float fn, int n4) {
    __shared__ float sc[16], sh2[16];
    int tid = threadIdx.x;
    if (tid < 16) {
        float m = stats[tid] / fn;
        float v = stats[16 + tid] / fn - m * m;
        v = fmaxf(v, 0.0f);
        float s = gamma[tid] * rsqrtf(v + 1e-5f);
        sc[tid] = s;
        sh2[tid] = beta[tid] - m * s;
    }
    __syncthreads();
    int idx = blockIdx.x * blockDim.x + tid;
    if (idx >= n4) return;
    int q = idx & 3;
    float di = g_dinv[idx >> 2];
    uint2 yw = g_hA[idx];
    float2 ylo = __half22float2(*(const __half2*)&yw.x);
    float2 yhi = __half22float2(*(const __half2*)&yw.y);
    float v0 = di * fmaxf(ylo.x * sc[q * 4 + 0] + sh2[q * 4 + 0], 0.0f);
    float v1 = di * fmaxf(ylo.y * sc[q * 4 + 1] + sh2[q * 4 + 1], 0.0f);
    float v2 = di * fmaxf(yhi.x * sc[q * 4 + 2] + sh2[q * 4 + 2], 0.0f);
    float v3 = di * fmaxf(yhi.y * sc[q * 4 + 3] + sh2[q * 4 + 3], 0.0f);
    __half2 lo = __float22half2_rn(make_float2(v0, v1));
    __half2 hi = __float22half2_rn(make_float2(v2, v3));
    g_hB[idx] = make_uint2(*(unsigned*)&lo, *(unsigned*)&hi);
}

// ---------------- host launcher ----------------

extern "C" void kernel_launch(void* const* d_in, const int* in_sizes, int n_in,
                              void* d_out, int out_size) {
    const float* x      = (const float*)d_in[0];
    const int*   ei     = (const int*)d_in[1];
    const float* W_in   = (const float*)d_in[2];
    const float* b_in   = (const float*)d_in[3];
    const float* Ws     = (const float*)d_in[4];
    const float* bs     = (const float*)d_in[5];
    const float* gammas = (const float*)d_in[6];
    const float* betas  = (const float*)d_in[7];
    const float* W_sin  = (const float*)d_in[8];
    const float* b_sin  = (const float*)d_in[9];
    const float* W_cos  = (const float*)d_in[10];
    const float* b_cos  = (const float*)d_in[11];
    float* out = (float*)d_out;

    int n = in_sizes[0] / 64;
    int E = in_sizes[1] / 2;
    int n4 = n * 4;

    int nbn  = (n + 255) / 256;
    int nbn4 = (n4 + 255) / 256;
    int nbe4 = ((E + 3) / 4 + 255) / 256;

    void* stats_ptr = nullptr;
    cudaGetSymbolAddress(&stats_ptr, g_stats);
    float* stats_base = (float*)stats_ptr;

    // ---- graph prep: slack-CSR single-pass fill (+ overlapped input proj) ----
    k_init<<<nbn, 256>>>(n);
    k_fill_xw<<<nbn + nbe4, 256>>>(ei, E, x, W_in, n, nbn);
    k_post<<<nbn, 256>>>(n);

    // ---- input layer aggregation ----
    k_agg_in<<<nbn4, 256>>>(b_in, n);

    // ---- 4 mid layers: agg+matmul+stats (y fp16) then streaming BN+relu ----
    for (int l = 0; l < 4; l++) {
        k_agg_mid<<<nbn4, 256>>>(Ws + l * 256, bs + l * 16, stats_base + l * 32, n);
        k_bn_relu<<<nbn4, 256>>>(stats_base + l * 32, gammas + l * 16, betas + l * 16,
                                 (float)n, n4);
    }

    // ---- heads: one aggregation fused with both output matmuls ----
    k_agg_head<<<nbn4, 256>>>(W_sin, b_sin, W_cos, b_cos, out, n);
}

// round 15
// speedup vs baseline: 1.0529x; 1.0529x over previous
#include <cuda_runtime.h>
#include <cuda_fp16.h>

#define NMAX 200000
#define SLACK 96                       // max supported degree per node (Poisson(32) tail ~4e-20)

// ---------------- static device scratch ----------------
static __device__ __align__(16) int g_csr[NMAX * SLACK];  // slack CSR: row i at [96*i, cursor[i])
static __device__ int   g_cursor[NMAX];
static __device__ float g_dinv[NMAX];
static __device__ float g_xw[NMAX * 16];       // fp32 x@W_in (pre-dinv)
static __device__ uint2 g_hA[NMAX * 4];        // layer-0 scaled input; then per-layer fp16 y
static __device__ uint2 g_hB[NMAX * 4];        // pre-scaled fp16x4 quarter-rows (agg input)
static __device__ float g_stats[4 * 32];       // per mid-layer [sum16, sumsq16] of y

// ---------------- helpers ----------------

// int64 entries (node ids < 2^31) have zero high words; int32 layout puts
// node ids there instead.
__device__ __forceinline__ bool is64_layout(const int* __restrict__ ei, int E) {
    int m = (E < 1024) ? E : 1024;
    int any = 0;
    for (int k = threadIdx.x; k < m; k += blockDim.x) any |= ei[2 * k + 1];
    return __syncthreads_or(any) == 0;
}

// ---------------- prep ----------------

// cursor[i] = SLACK*i; block 0 zeroes the BN stats.
__global__ void k_init(int n) {
    int i = blockIdx.x * blockDim.x + threadIdx.x;
    if (i < n) g_cursor[i] = i * SLACK;
    if (blockIdx.x == 0 && threadIdx.x < 128) g_stats[threadIdx.x] = 0.0f;
}

// Fused kernel: blocks [0, nbn) compute g_xw = x@W_in (fp32, DRAM+FMA bound,
// scheduled first so DRAM reads start in wave 1); blocks [nbn, nbn+nbe4) fill
// the slack CSR in a single atomic pass (LTS-atomic bound).
// __launch_bounds__(256, 8) caps regs at 32 so the fill half keeps occupancy.
__global__ void __launch_bounds__(256, 8)
k_fill_xw(const int* __restrict__ ei, int E,
          const float* __restrict__ x, const float* __restrict__ W,
          int n, int nbn) {
    int tid = threadIdx.x;
    if ((int)blockIdx.x >= nbn) {
        // ---- CSR fill: 4 edges per thread ----
        bool is64 = is64_layout(ei, E);
        int t = ((int)blockIdx.x - nbn) * blockDim.x + tid;
        int e0 = t * 4;
        bool vec = is64 ? ((E & 1) == 0) : ((E & 3) == 0);
        if (vec && e0 + 4 <= E) {
            int s0, s1, s2, s3, d0, d1, d2, d3;
            if (is64) {
                const int4* ps = (const int4*)ei;
                const int4* pd = (const int4*)(ei + 2 * E);
                int4 sa = ps[2 * t], sb = ps[2 * t + 1];
                int4 da = pd[2 * t], db = pd[2 * t + 1];
                s0 = sa.x; s1 = sa.z; s2 = sb.x; s3 = sb.z;
                d0 = da.x; d1 = da.z; d2 = db.x; d3 = db.z;
            } else {
                int4 s = ((const int4*)ei)[t];
                int4 d = ((const int4*)(ei + E))[t];
                s0 = s.x; s1 = s.y; s2 = s.z; s3 = s.w;
                d0 = d.x; d1 = d.y; d2 = d.z; d3 = d.w;
            }
            int p0 = atomicAdd(&g_cursor[d0], 1);
            int p1 = atomicAdd(&g_cursor[d1], 1);
            int p2 = atomicAdd(&g_cursor[d2], 1);
            int p3 = atomicAdd(&g_cursor[d3], 1);
            g_csr[p0] = s0;
            g_csr[p1] = s1;
            g_csr[p2] = s2;
            g_csr[p3] = s3;
        } else {
            for (int e = e0; e < E && e < e0 + 4; e++) {
                int s, d;
                if (is64) { s = ei[2 * e]; d = ei[2 * E + 2 * e]; }
                else      { s = ei[e];     d = ei[E + e]; }
                g_csr[atomicAdd(&g_cursor[d], 1)] = s;
            }
        }
    } else {
        // ---- input projection: g_xw = x @ W_in (fp32, no dinv yet) ----
        __shared__ float sW[64 * 16];
        ((float4*)sW)[tid] = ((const float4*)W)[tid];
        __syncthreads();
        int row = (int)blockIdx.x * 256 + tid;
        if (row >= n) return;
        const float4* xr = (const float4*)(x + (size_t)row * 64);
        float y[16];
#pragma unroll
        for (int j = 0; j < 16; j++) y[j] = 0.0f;
#pragma unroll
        for (int k4 = 0; k4 < 16; k4++) {
            float4 xv = xr[k4];
            int kb = k4 * 4;
#pragma unroll
            for (int j = 0; j < 16; j++) y[j] += xv.x * sW[(kb + 0) * 16 + j];
#pragma unroll
            for (int j = 0; j < 16; j++) y[j] += xv.y * sW[(kb + 1) * 16 + j];
#pragma unroll
            for (int j = 0; j < 16; j++) y[j] += xv.z * sW[(kb + 2) * 16 + j];
#pragma unroll
            for (int j = 0; j < 16; j++) y[j] += xv.w * sW[(kb + 3) * 16 + j];
        }
        float4* o = (float4*)(g_xw + (size_t)row * 16);
        o[0] = make_float4(y[0], y[1], y[2], y[3]);
        o[1] = make_float4(y[4], y[5], y[6], y[7]);
        o[2] = make_float4(y[8], y[9], y[10], y[11]);
        o[3] = make_float4(y[12], y[13], y[14], y[15]);
    }
}

// post-fill: dinv from cursor-derived degree; g_hA = fp16(dinv * g_xw)
__global__ void k_post(int n) {
    int i = blockIdx.x * blockDim.x + threadIdx.x;
    if (i >= n) return;
    int deg = g_cursor[i] - i * SLACK;
    float di = rsqrtf((float)deg + 1.0f);  // +1 self loop
    g_dinv[i] = di;
    const float4* X = (const float4*)(g_xw + (size_t)i * 16);
    uint2* o = g_hA + (size_t)i * 4;
#pragma unroll
    for (int q = 0; q < 4; q++) {
        float4 v = X[q];
        __half2 lo = __float22half2_rn(make_float2(v.x * di, v.y * di));
        __half2 hi = __float22half2_rn(make_float2(v.z * di, v.w * di));
        o[q] = make_uint2(*(unsigned*)&lo, *(unsigned*)&hi);
    }
}

// ---------------- aggregation core ----------------
// 4 lanes per node; lane q owns channels [4q,4q+4). Features pre-scaled (hs=dinv*h):
// sum_raw = sum_{s in N(d)} hs[s] + hs[d]; caller scales by dinv[d].
// Row extent: [SLACK*i, cursor[i]). CSR entries shared via width-4 shuffles.
// Edge PAIRS are pre-reduced in fp16 (2 HADD2) before conversion, cutting the
// convert+add instruction stream ~30%. Callers carry __launch_bounds__(256, 8)
// so ptxas keeps regs <= 32 (R14 showed 34 regs -> occupancy collapse).
__device__ __forceinline__ float4 agg_core(const uint2* __restrict__ H, int i, int q,
                                           unsigned gmask) {
    uint2 self = H[(size_t)i * 4 + q];
    float2 slo = __half22float2(*(const __half2*)&self.x);
    float2 shi = __half22float2(*(const __half2*)&self.y);
    float4 acc = make_float4(slo.x, slo.y, shi.x, shi.y);
    int e = i * SLACK;
    int e1 = g_cursor[i];
    for (; e + 8 <= e1; e += 8) {
        int sA = g_csr[e + q];
        int sB = g_csr[e + 4 + q];
#pragma unroll
        for (int r = 0; r < 4; r++) {
            int s0 = __shfl_sync(gmask, sA, r, 4);
            int s1 = __shfl_sync(gmask, sB, r, 4);
            uint2 v0 = H[(size_t)s0 * 4 + q];
            uint2 v1 = H[(size_t)s1 * 4 + q];
            __half2 plo = __hadd2(*(const __half2*)&v0.x, *(const __half2*)&v1.x);
            __half2 phi = __hadd2(*(const __half2*)&v0.y, *(const __half2*)&v1.y);
            float2 l = __half22float2(plo);
            float2 h = __half22float2(phi);
            acc.x += l.x; acc.y += l.y; acc.z += h.x; acc.w += h.y;
        }
    }
    if (e + 4 <= e1) {
        int sA = g_csr[e + q];
#pragma unroll
        for (int r = 0; r < 2; r++) {
            int s0 = __shfl_sync(gmask, sA, 2 * r + 0, 4);
            int s1 = __shfl_sync(gmask, sA, 2 * r + 1, 4);
            uint2 v0 = H[(size_t)s0 * 4 + q];
            uint2 v1 = H[(size_t)s1 * 4 + q];
            __half2 plo = __hadd2(*(const __half2*)&v0.x, *(const __half2*)&v1.x);
            __half2 phi = __hadd2(*(const __half2*)&v0.y, *(const __half2*)&v1.y);
            float2 l = __half22float2(plo);
            float2 h = __half22float2(phi);
            acc.x += l.x; acc.y += l.y; acc.z += h.x; acc.w += h.y;
        }
        e += 4;
    }
    for (; e < e1; e++) {
        int s = g_csr[e];
        uint2 v = H[(size_t)s * 4 + q];
        float2 lo = __half22float2(*(const __half2*)&v.x);
        float2 hi = __half22float2(*(const __half2*)&v.y);
        acc.x += lo.x; acc.y += lo.y; acc.z += hi.x; acc.w += hi.y;
    }
    return acc;
}

// input layer: h1 = dinv[d]*sum + b_in; store hB = fp16(dinv[d] * h1)
__global__ void __launch_bounds__(256, 8)
k_agg_in(const float* __restrict__ b, int n) {
    int idx = blockIdx.x * blockDim.x + threadIdx.x;
    if (idx >= n * 4) return;
    int i = idx >> 2, q = idx & 3;
    unsigned gmask = 0xFu << ((threadIdx.x & 31) & ~3);
    float4 acc = agg_core(g_hA, i, q, gmask);
    float di = g_dinv[i];
    float4 bb = ((const float4*)b)[q];
    acc.x = (acc.x * di + bb.x) * di;
    acc.y = (acc.y * di + bb.y) * di;
    acc.z = (acc.z * di + bb.z) * di;
    acc.w = (acc.w * di + bb.w) * di;
    __half2 lo = __float22half2_rn(make_float2(acc.x, acc.y));
    __half2 hi = __float22half2_rn(make_float2(acc.z, acc.w));
    g_hB[(size_t)i * 4 + q] = make_uint2(*(unsigned*)&lo, *(unsigned*)&hi);
}

// mid agg: compute a = dinv[d]*sum, y = a@W + b; store y as fp16 into g_hA,
// and accumulate per-channel sum/sumsq of y into stats.
__global__ void __launch_bounds__(256, 8)
k_agg_mid(const float* __restrict__ W, const float* __restrict__ b,
          float* __restrict__ stats, int n) {
    __shared__ float sW[256];
    __shared__ float sB[16];
    __shared__ float sSum[16], sSq[16];
    int tid = threadIdx.x;
    sW[tid] = W[tid];
    if (tid < 16) { sB[tid] = b[tid]; sSum[tid] = 0.0f; sSq[tid] = 0.0f; }
    __syncthreads();
    int idx = blockIdx.x * blockDim.x + tid;
    bool valid = idx < n * 4;
    int i = valid ? (idx >> 2) : 0;
    int q = idx & 3;
    int lane = tid & 31;
    unsigned gmask = 0xFu << (lane & ~3);
    float4 acc = agg_core(g_hB, i, q, gmask);
    float di = g_dinv[i];
    acc.x *= di; acc.y *= di; acc.z *= di; acc.w *= di;
    // assemble full 16-vector of node i across the 4-lane group
    float af[16];
    int base = lane & ~3;
#pragma unroll
    for (int r = 0; r < 4; r++) {
        af[r * 4 + 0] = __shfl_sync(0xFFFFFFFFu, acc.x, base + r);
        af[r * 4 + 1] = __shfl_sync(0xFFFFFFFFu, acc.y, base + r);
        af[r * 4 + 2] = __shfl_sync(0xFFFFFFFFu, acc.z, base + r);
        af[r * 4 + 3] = __shfl_sync(0xFFFFFFFFu, acc.w, base + r);
    }
    // this lane computes y for its 4 channels
    float s4[4], q4[4];
#pragma unroll
    for (int m = 0; m < 4; m++) {
        float y = sB[q * 4 + m];
#pragma unroll
        for (int k = 0; k < 16; k++) y += af[k] * sW[k * 16 + q * 4 + m];
        if (!valid) y = 0.0f;
        s4[m] = y;
        q4[m] = y * y;
    }
    // store y as fp16 (before the stats reduction clobbers s4)
    if (valid) {
        __half2 lo = __float22half2_rn(make_float2(s4[0], s4[1]));
        __half2 hi = __float22half2_rn(make_float2(s4[2], s4[3]));
        g_hA[(size_t)i * 4 + q] = make_uint2(*(unsigned*)&lo, *(unsigned*)&hi);
    }
    // reduce across the 8 groups in the warp
#pragma unroll
    for (int off = 4; off < 32; off <<= 1) {
#pragma unroll
        for (int m = 0; m < 4; m++) {
            s4[m] += __shfl_xor_sync(0xFFFFFFFFu, s4[m], off);
            q4[m] += __shfl_xor_sync(0xFFFFFFFFu, q4[m], off);
        }
    }
    if (lane < 4) {
#pragma unroll
        for (int m = 0; m < 4; m++) {
            atomicAdd(&sSum[lane * 4 + m], s4[m]);
            atomicAdd(&sSq[lane * 4 + m], q4[m]);
        }
    }
    __syncthreads();
    if (tid < 16) {
        atomicAdd(&stats[tid], sSum[tid]);
        atomicAdd(&stats[16 + tid], sSq[tid]);
    }
}

// head agg + dual matmul + relu fused: out = [relu(a@Wsin+bsin); relu(a@Wcos+bcos)]
__global__ void __launch_bounds__(256, 8)
k_agg_head(const float* __restrict__ Wsin, const float* __restrict__ bsin,
           const float* __restrict__ Wcos, const float* __restrict__ bcos,
           float* __restrict__ out, int n) {
    __shared__ float sWs[256], sWc[256];
    __shared__ float sBs[16], sBc[16];
    int tid = threadIdx.x;
    sWs[tid] = Wsin[tid];
    sWc[tid] = Wcos[tid];
    if (tid < 16) { sBs[tid] = bsin[tid]; sBc[tid] = bcos[tid]; }
    __syncthreads();
    int idx = blockIdx.x * blockDim.x + tid;
    bool valid = idx < n * 4;
    int i = valid ? (idx >> 2) : 0;
    int q = idx & 3;
    int lane = tid & 31;
    unsigned gmask = 0xFu << (lane & ~3);
    float4 acc = agg_core(g_hB, i, q, gmask);
    float di = g_dinv[i];
    acc.x *= di; acc.y *= di; acc.z *= di; acc.w *= di;
    float af[16];
    int base = lane & ~3;
#pragma unroll
    for (int r = 0; r < 4; r++) {
        af[r * 4 + 0] = __shfl_sync(0xFFFFFFFFu, acc.x, base + r);
        af[r * 4 + 1] = __shfl_sync(0xFFFFFFFFu, acc.y, base + r);
        af[r * 4 + 2] = __shfl_sync(0xFFFFFFFFu, acc.z, base + r);
        af[r * 4 + 3] = __shfl_sync(0xFFFFFFFFu, acc.w, base + r);
    }
    if (!valid) return;
    float ys[4], yc[4];
#pragma unroll
    for (int m = 0; m < 4; m++) { ys[m] = sBs[q * 4 + m]; yc[m] = sBc[q * 4 + m]; }
#pragma unroll
    for (int k = 0; k < 16; k++) {
        float av = af[k];
#pragma unroll
        for (int m = 0; m < 4; m++) {
            ys[m] += av * sWs[k * 16 + q * 4 + m];
            yc[m] += av * sWc[k * 16 + q * 4 + m];
        }
    }
    float4 os = make_float4(fmaxf(ys[0], 0.0f), fmaxf(ys[1], 0.0f),
                            fmaxf(ys[2], 0.0f), fmaxf(ys[3], 0.0f));
    float4 oc = make_float4(fmaxf(yc[0], 0.0f), fmaxf(yc[1], 0.0f),
                            fmaxf(yc[2], 0.0f), fmaxf(yc[3], 0.0f));
    ((float4*)(out))[(size_t)i * 4 + q] = os;
    ((float4*)(out + (size_t)n * 16))[(size_t)i * 4 + q] = oc;
}

// hB = fp16(dinv * relu(y*sc + shift))  — streams fp16 y from g_hA.
// Bias is already inside y, so shift = beta - mean*sc.
__global__ void k_bn_relu(const float* __restrict__ stats,
                          const float* __restrict__ gamma, const float* __restrict__ beta,
                          float fn, int n4) {
    __shared__ float sc[16], sh2[16];
    int tid = threadIdx.x;
    if (tid < 16) {
        float m = stats[tid] / fn;
        float v = stats[16 + tid] / fn - m * m;
        v = fmaxf(v, 0.0f);
        float s = gamma[tid] * rsqrtf(v + 1e-5f);
        sc[tid] = s;
        sh2[tid] = beta[tid] - m * s;
    }
    __syncthreads();
    int idx = blockIdx.x * blockDim.x + tid;
    if (idx >= n4) return;
    int q = idx & 3;
    float di = g_dinv[idx >> 2];
    uint2 yw = g_hA[idx];
    float2 ylo = __half22float2(*(const __half2*)&yw.x);
    float2 yhi = __half22float2(*(const __half2*)&yw.y);
    float v0 = di * fmaxf(ylo.x * sc[q * 4 + 0] + sh2[q * 4 + 0], 0.0f);
    float v1 = di * fmaxf(ylo.y * sc[q * 4 + 1] + sh2[q * 4 + 1], 0.0f);
    float v2 = di * fmaxf(yhi.x * sc[q * 4 + 2] + sh2[q * 4 + 2], 0.0f);
    float v3 = di * fmaxf(yhi.y * sc[q * 4 + 3] + sh2[q * 4 + 3], 0.0f);
    __half2 lo = __float22half2_rn(make_float2(v0, v1));
    __half2 hi = __float22half2_rn(make_float2(v2, v3));
    g_hB[idx] = make_uint2(*(unsigned*)&lo, *(unsigned*)&hi);
}

// ---------------- host launcher ----------------

extern "C" void kernel_launch(void* const* d_in, const int* in_sizes, int n_in,
                              void* d_out, int out_size) {
    const float* x      = (const float*)d_in[0];
    const int*   ei     = (const int*)d_in[1];
    const float* W_in   = (const float*)d_in[2];
    const float* b_in   = (const float*)d_in[3];
    const float* Ws     = (const float*)d_in[4];
    const float* bs     = (const float*)d_in[5];
    const float* gammas = (const float*)d_in[6];
    const float* betas  = (const float*)d_in[7];
    const float* W_sin  = (const float*)d_in[8];
    const float* b_sin  = (const float*)d_in[9];
    const float* W_cos  = (const float*)d_in[10];
    const float* b_cos  = (const float*)d_in[11];
    float* out = (float*)d_out;

    int n = in_sizes[0] / 64;
    int E = in_sizes[1] / 2;
    int n4 = n * 4;

    int nbn  = (n + 255) / 256;
    int nbn4 = (n4 + 255) / 256;
    int nbe4 = ((E + 3) / 4 + 255) / 256;

    void* stats_ptr = nullptr;
    cudaGetSymbolAddress(&stats_ptr, g_stats);
    float* stats_base = (float*)stats_ptr;

    // ---- graph prep: slack-CSR single-pass fill (+ overlapped input proj) ----
    k_init<<<nbn, 256>>>(n);
    k_fill_xw<<<nbn + nbe4, 256>>>(ei, E, x, W_in, n, nbn);
    k_post<<<nbn, 256>>>(n);

    // ---- input layer aggregation ----
    k_agg_in<<<nbn4, 256>>>(b_in, n);

    // ---- 4 mid layers: agg+matmul+stats (y fp16) then streaming BN+relu ----
    for (int l = 0; l < 4; l++) {
        k_agg_mid<<<nbn4, 256>>>(Ws + l * 256, bs + l * 16, stats_base + l * 32, n);
        k_bn_relu<<<nbn4, 256>>>(stats_base + l * 32, gammas + l * 16, betas + l * 16,
                                 (float)n, n4);
    }

    // ---- heads: one aggregation fused with both output matmuls ----
    k_agg_head<<<nbn4, 256>>>(W_sin, b_sin, W_cos, b_cos, out, n);
}